// round 2
// baseline (speedup 1.0000x reference)
#include <cuda_runtime.h>
#include <cuda_fp16.h>
#include <cstdint>

// ---------------- problem dims (fixed) ----------------
#define QB 32
#define QT 1024
#define QD 1152
#define QH 4608
#define QM (QB*QT)          // 32768 tokens

// ---------------- scratch (__device__ globals; no cudaMalloc allowed) ------
__device__ __half  g_q1[(size_t)QM*QD];       // quantized input (exact ints in fp16)
__device__ float   g_scale1[QM];
__device__ __half  g_w1hi[(size_t)QH*QD];
__device__ __half  g_w1lo[(size_t)QH*QD];     // (W1 - hi)*2048
__device__ __half  g_w2h [(size_t)QD*QH];
__device__ float   g_h   [(size_t)QM*QH];     // fc1 output (fp32, post-GELU)
__device__ float   g_scale2[QM];
__device__ __half  g_q2[(size_t)QM*QH];

// ---------------- low-level helpers ----------------
__device__ __forceinline__ uint32_t smem_u32(const void* p){
    uint32_t a;
    asm("{ .reg .u64 t; cvta.to.shared.u64 t, %1; cvt.u32.u64 %0, t; }" : "=r"(a) : "l"(p));
    return a;
}
__device__ __forceinline__ void cp16(uint32_t saddr, const void* g){
    asm volatile("cp.async.cg.shared.global [%0], [%1], 16;" :: "r"(saddr), "l"(g));
}
#define CP_COMMIT() asm volatile("cp.async.commit_group;" ::: "memory")
#define CP_WAIT(n)  asm volatile("cp.async.wait_group %0;" :: "n"(n) : "memory")

__device__ __forceinline__ void ldsm_x4(uint32_t& r0,uint32_t& r1,uint32_t& r2,uint32_t& r3,uint32_t a){
    asm volatile("ldmatrix.sync.aligned.m8n8.x4.shared.b16 {%0,%1,%2,%3}, [%4];"
        : "=r"(r0),"=r"(r1),"=r"(r2),"=r"(r3) : "r"(a));
}
__device__ __forceinline__ void ldsm_x2(uint32_t& r0,uint32_t& r1,uint32_t a){
    asm volatile("ldmatrix.sync.aligned.m8n8.x2.shared.b16 {%0,%1}, [%2];"
        : "=r"(r0),"=r"(r1) : "r"(a));
}
__device__ __forceinline__ void mma16816(float* d, const uint32_t* a, const uint32_t* b){
    asm volatile("mma.sync.aligned.m16n8k16.row.col.f32.f16.f16.f32 "
        "{%0,%1,%2,%3},{%4,%5,%6,%7},{%8,%9},{%0,%1,%2,%3};"
        : "+f"(d[0]),"+f"(d[1]),"+f"(d[2]),"+f"(d[3])
        : "r"(a[0]),"r"(a[1]),"r"(a[2]),"r"(a[3]), "r"(b[0]),"r"(b[1]));
}

// swizzled byte offset of 16B chunk (r, c) in a [128 rows x 64B] tile.
// chunk' = c ^ ((r>>1)&3) plus the r&1 64B shift gives 8 distinct 16B phases
// across any 8 consecutive rows -> conflict-free ldmatrix and cp.async stores.
__device__ __forceinline__ uint32_t sw_off(int r, int c){
    return (uint32_t)(r*64 + ((c ^ ((r>>1)&3))*16));
}

__device__ __forceinline__ float gelu_exact(float v){
    return 0.5f * v * (1.0f + erff(v * 0.70710678118654752440f));
}

// ---------------- elementwise kernels ----------------

// per-token quantize of (reordered) x -> g_q1 (exact small ints in fp16)
__global__ void __launch_bounds__(128) quant_x_kernel(const float* __restrict__ x,
                                                      const int* __restrict__ ridx){
    int row = blockIdx.x;
    const float* xr = x + (size_t)row * QD;
    float v[9]; float mx = 0.f;
    int tid = threadIdx.x;
#pragma unroll
    for (int i = 0; i < 9; i++){
        int d = tid + i*128;
        v[i] = xr[ridx[d]];
        mx = fmaxf(mx, fabsf(v[i]));
    }
#pragma unroll
    for (int o = 16; o > 0; o >>= 1) mx = fmaxf(mx, __shfl_xor_sync(0xffffffffu, mx, o));
    __shared__ float wmax[4];
    if ((tid & 31) == 0) wmax[tid >> 5] = mx;
    __syncthreads();
    mx = fmaxf(fmaxf(wmax[0], wmax[1]), fmaxf(wmax[2], wmax[3]));
    float scale = fmaxf(mx * (1.0f/127.0f), 1e-8f);
    if (tid == 0) g_scale1[row] = scale;
    __half* qr = g_q1 + (size_t)row * QD;
#pragma unroll
    for (int i = 0; i < 9; i++){
        int d = tid + i*128;
        float q = rintf(v[i] / scale);
        q = fminf(fmaxf(q, -128.f), 127.f);
        qr[d] = __float2half_rn(q);   // exact (|q| <= 128)
    }
}

// W1 -> fp16 hi/lo split (lo pre-scaled by 2048); W2 -> fp16
__global__ void __launch_bounds__(256) convert_w_kernel(const float* __restrict__ W1,
                                                        const float* __restrict__ W2){
    size_t i = (size_t)blockIdx.x * blockDim.x + threadIdx.x;
    size_t N = (size_t)QH * QD;
    if (i >= N) return;
    float w = W1[i];
    __half hi = __float2half_rn(w);
    g_w1hi[i] = hi;
    g_w1lo[i] = __float2half_rn((w - __half2float(hi)) * 2048.0f);
    g_w2h[i]  = __float2half_rn(W2[i]);
}

// per-token row-max + quantize of h -> g_q2
__global__ void __launch_bounds__(256) quant_h_kernel(){
    int row = blockIdx.x;
    int tid = threadIdx.x;
    const float* hr = g_h + (size_t)row * QH;
    float v[18]; float mx = 0.f;
#pragma unroll
    for (int i = 0; i < 18; i++){
        v[i] = hr[tid + i*256];
        mx = fmaxf(mx, fabsf(v[i]));
    }
#pragma unroll
    for (int o = 16; o > 0; o >>= 1) mx = fmaxf(mx, __shfl_xor_sync(0xffffffffu, mx, o));
    __shared__ float wmax[8];
    if ((tid & 31) == 0) wmax[tid >> 5] = mx;
    __syncthreads();
    mx = 0.f;
#pragma unroll
    for (int i = 0; i < 8; i++) mx = fmaxf(mx, wmax[i]);
    float s = fmaxf(mx * (1.0f/127.0f), 1e-8f);
    if (tid == 0) g_scale2[row] = s;
    __half* qr = g_q2 + (size_t)row * QH;
#pragma unroll
    for (int i = 0; i < 18; i++){
        int d = tid + i*256;
        float q = rintf(v[i] / s);
        q = fminf(fmaxf(q, -128.f), 127.f);
        qr[d] = __float2half_rn(q);
    }
}

// ---------------- HMMA GEMM: 128x128x32 CTA tile, 8 warps (64x32 each) -----
constexpr int BM = 128, BN = 128, BK = 32;
constexpr int TILEB = BM * 64;   // one [128 x 32] fp16 tile = 8192 B

// FC1: acc_hi += q1*W1hi, acc_lo += q1*W1lo; epi: gelu((hi+lo/2048)*s1+b1) -> g_h
// FC2: acc    += q2*W2h ;                    epi: acc*s2+b2 -> out
template<bool FC1>
__global__ void __launch_bounds__(256)
gemm_kernel(const float* __restrict__ bias, float* __restrict__ outArg){
    const __half* __restrict__ A   = FC1 ? g_q1   : g_q2;
    const __half* __restrict__ Bh  = FC1 ? g_w1hi : g_w2h;
    const __half* __restrict__ Bl  = g_w1lo;
    const float*  __restrict__ rsc = FC1 ? g_scale1 : g_scale2;
    float* __restrict__ outF       = FC1 ? (float*)g_h : outArg;
    const int K = FC1 ? QD : QH;
    const int N = FC1 ? QH : QD;

    extern __shared__ __align__(128) char smem[];
    uint32_t sAb  = smem_u32(smem);                 // stages 0,1: A
    uint32_t sBhb = sAb + 2*TILEB;                  // stages 0,1: B hi
    uint32_t sBlb = sAb + 4*TILEB;                  // stages 0,1: B lo (FC1 only)

    int tid = threadIdx.x;
    int lane = tid & 31, wid = tid >> 5;
    int wm = wid >> 2, wn = wid & 3;                // warp grid 2 (m) x 4 (n)
    int m0 = blockIdx.y * BM, n0 = blockIdx.x * BN;
    const int NK = K / BK;

    float acc_h[4][4][4];
    float acc_l[FC1 ? 4 : 1][4][4];
#pragma unroll
    for (int mt=0; mt<4; mt++)
#pragma unroll
        for (int nt=0; nt<4; nt++)
#pragma unroll
            for (int j=0; j<4; j++){
                acc_h[mt][nt][j] = 0.f;
                if (FC1) acc_l[mt][nt][j] = 0.f;
            }

    auto load_stage = [&](int kt, int st){
        size_t k0 = (size_t)kt * BK;
        uint32_t sb = st * TILEB;
#pragma unroll
        for (int i = 0; i < 2; i++){
            int ch = tid + i*256;          // 512 16B-chunks per tile
            int r = ch >> 2, c = ch & 3;
            uint32_t so = sb + sw_off(r, c);
            cp16(sAb  + so, A  + (size_t)(m0 + r)*K + k0 + c*8);
            cp16(sBhb + so, Bh + (size_t)(n0 + r)*K + k0 + c*8);
            if (FC1)
                cp16(sBlb + so, Bl + (size_t)(n0 + r)*K + k0 + c*8);
        }
    };

    auto compute = [&](int st){
        uint32_t sb = st * TILEB;
#pragma unroll
        for (int kt = 0; kt < 2; kt++){
            uint32_t af[4][4];
#pragma unroll
            for (int mt = 0; mt < 4; mt++){
                int r = wm*64 + mt*16 + (lane & 15);
                int c = kt*2 + (lane >> 4);
                ldsm_x4(af[mt][0],af[mt][1],af[mt][2],af[mt][3], sAb + sb + sw_off(r, c));
            }
            uint32_t bhf[4][2], blf[4][2];
#pragma unroll
            for (int nt = 0; nt < 4; nt++){
                int r = wn*32 + nt*8 + (lane & 7);
                int c = kt*2 + ((lane >> 3) & 1);
                ldsm_x2(bhf[nt][0], bhf[nt][1], sBhb + sb + sw_off(r, c));
                if (FC1)
                    ldsm_x2(blf[nt][0], blf[nt][1], sBlb + sb + sw_off(r, c));
            }
#pragma unroll
            for (int mt = 0; mt < 4; mt++)
#pragma unroll
                for (int nt = 0; nt < 4; nt++){
                    mma16816(acc_h[mt][nt], af[mt], bhf[nt]);
                    if (FC1) mma16816(acc_l[mt][nt], af[mt], blf[nt]);
                }
        }
    };

    load_stage(0, 0);
    CP_COMMIT();
    for (int kt = 0; kt < NK; kt++){
        int st = kt & 1;
        if (kt + 1 < NK){
            load_stage(kt + 1, st ^ 1);
            CP_COMMIT();
            CP_WAIT(1);
        } else {
            CP_WAIT(0);
        }
        __syncthreads();
        compute(st);
        __syncthreads();
    }

    // ---- epilogue ----
#pragma unroll
    for (int mt = 0; mt < 4; mt++){
#pragma unroll
        for (int hf = 0; hf < 2; hf++){
            int row = m0 + wm*64 + mt*16 + (lane >> 2) + 8*hf;
            float s = rsc[row];
#pragma unroll
            for (int nt = 0; nt < 4; nt++){
                int col = n0 + wn*32 + nt*8 + (lane & 3)*2;
                float v0 = acc_h[mt][nt][hf*2 + 0];
                float v1 = acc_h[mt][nt][hf*2 + 1];
                if (FC1){
                    v0 += acc_l[mt][nt][hf*2 + 0] * (1.0f/2048.0f);
                    v1 += acc_l[mt][nt][hf*2 + 1] * (1.0f/2048.0f);
                }
                v0 = v0 * s + bias[col];
                v1 = v1 * s + bias[col + 1];
                if (FC1){
                    v0 = gelu_exact(v0);
                    v1 = gelu_exact(v1);
                }
                *(float2*)(outF + (size_t)row * N + col) = make_float2(v0, v1);
            }
        }
    }
}

// ---------------- launch ----------------
extern "C" void kernel_launch(void* const* d_in, const int* in_sizes, int n_in,
                              void* d_out, int out_size){
    (void)in_sizes; (void)n_in; (void)out_size;
    const float* x    = (const float*)d_in[0];
    const int*   ridx = (const int*)  d_in[1];
    const float* W1   = (const float*)d_in[2];
    const float* b1   = (const float*)d_in[3];
    const float* W2   = (const float*)d_in[4];
    const float* b2   = (const float*)d_in[5];
    float* out = (float*)d_out;

    const int SMEM1 = 6 * TILEB;   // 49152 B
    const int SMEM2 = 4 * TILEB;   // 32768 B
    static bool attr_set = false;
    if (!attr_set){
        cudaFuncSetAttribute(gemm_kernel<true>,  cudaFuncAttributeMaxDynamicSharedMemorySize, SMEM1);
        cudaFuncSetAttribute(gemm_kernel<false>, cudaFuncAttributeMaxDynamicSharedMemorySize, SMEM2);
        attr_set = true;
    }

    quant_x_kernel<<<QM, 128>>>(x, ridx);
    {
        size_t Nw = (size_t)QH * QD;
        convert_w_kernel<<<(unsigned)((Nw + 255) / 256), 256>>>(W1, W2);
    }
    gemm_kernel<true> <<<dim3(QH / BN, QM / BM), 256, SMEM1>>>(b1, nullptr);
    quant_h_kernel<<<QM, 256>>>();
    gemm_kernel<false><<<dim3(QD / BN, QM / BM), 256, SMEM2>>>(b2, out);
}

// round 4
// speedup vs baseline: 1.0926x; 1.0926x over previous
#include <cuda_runtime.h>
#include <cuda_fp16.h>
#include <cstdint>

// ---------------- problem dims (fixed) ----------------
#define QB 32
#define QT 1024
#define QD 1152
#define QH 4608
#define QM (QB*QT)          // 32768 tokens

// ---------------- scratch (__device__ globals) ------
__device__ __half  g_q1[(size_t)QM*QD];       // quantized input (exact ints in fp16)
__device__ float   g_scale1[QM];
__device__ __half  g_w1hi[(size_t)QH*QD];
__device__ __half  g_w1lo[(size_t)QH*QD];     // TRUE residual w - fp16(w) (subnormal ok)
__device__ __half  g_w2h [(size_t)QD*QH];
__device__ float   g_h   [(size_t)QM*QH];     // fc1 output (fp32, post-GELU)
__device__ float   g_scale2[QM];
__device__ __half  g_q2[(size_t)QM*QH];

// ---------------- low-level helpers ----------------
__device__ __forceinline__ uint32_t smem_u32(const void* p){
    uint32_t a;
    asm("{ .reg .u64 t; cvta.to.shared.u64 t, %1; cvt.u32.u64 %0, t; }" : "=r"(a) : "l"(p));
    return a;
}
__device__ __forceinline__ void cp16(uint32_t saddr, const void* g){
    asm volatile("cp.async.cg.shared.global [%0], [%1], 16;" :: "r"(saddr), "l"(g));
}
#define CP_COMMIT() asm volatile("cp.async.commit_group;" ::: "memory")
#define CP_WAIT(n)  asm volatile("cp.async.wait_group %0;" :: "n"(n) : "memory")

__device__ __forceinline__ void ldsm_x4(uint32_t* r, uint32_t a){
    asm volatile("ldmatrix.sync.aligned.m8n8.x4.shared.b16 {%0,%1,%2,%3}, [%4];"
        : "=r"(r[0]),"=r"(r[1]),"=r"(r[2]),"=r"(r[3]) : "r"(a));
}
__device__ __forceinline__ void mma16816(float* d, const uint32_t* a, const uint32_t* b){
    asm volatile("mma.sync.aligned.m16n8k16.row.col.f32.f16.f16.f32 "
        "{%0,%1,%2,%3},{%4,%5,%6,%7},{%8,%9},{%0,%1,%2,%3};"
        : "+f"(d[0]),"+f"(d[1]),"+f"(d[2]),"+f"(d[3])
        : "r"(a[0]),"r"(a[1]),"r"(a[2]),"r"(a[3]), "r"(b[0]),"r"(b[1]));
}

// swizzled byte offset of 16B chunk (r, c) in a [rows x 64B] tile (conflict-free)
__device__ __forceinline__ uint32_t sw_off(int r, int c){
    return (uint32_t)(r*64 + ((c ^ ((r>>1)&3))*16));
}
__device__ __forceinline__ float gelu_exact(float v){
    return 0.5f * v * (1.0f + erff(v * 0.70710678118654752440f));
}

// ---------------- elementwise kernels ----------------
__global__ void __launch_bounds__(128) quant_x_kernel(const float* __restrict__ x,
                                                      const int* __restrict__ ridx){
    int row = blockIdx.x;
    const float* xr = x + (size_t)row * QD;
    float v[9]; float mx = 0.f;
    int tid = threadIdx.x;
#pragma unroll
    for (int i = 0; i < 9; i++){
        int d = tid + i*128;
        v[i] = xr[ridx[d]];
        mx = fmaxf(mx, fabsf(v[i]));
    }
#pragma unroll
    for (int o = 16; o > 0; o >>= 1) mx = fmaxf(mx, __shfl_xor_sync(0xffffffffu, mx, o));
    __shared__ float wmax[4];
    if ((tid & 31) == 0) wmax[tid >> 5] = mx;
    __syncthreads();
    mx = fmaxf(fmaxf(wmax[0], wmax[1]), fmaxf(wmax[2], wmax[3]));
    float scale = fmaxf(mx * (1.0f/127.0f), 1e-8f);
    if (tid == 0) g_scale1[row] = scale;
    __half* qr = g_q1 + (size_t)row * QD;
#pragma unroll
    for (int i = 0; i < 9; i++){
        int d = tid + i*128;
        float q = rintf(v[i] / scale);
        q = fminf(fmaxf(q, -128.f), 127.f);
        qr[d] = __float2half_rn(q);
    }
}

__global__ void __launch_bounds__(256) convert_w_kernel(const float* __restrict__ W1,
                                                        const float* __restrict__ W2){
    size_t i = (size_t)blockIdx.x * blockDim.x + threadIdx.x;
    size_t N = (size_t)QH * QD;
    if (i >= N) return;
    float w = W1[i];
    __half hi = __float2half_rn(w);
    g_w1hi[i] = hi;
    g_w1lo[i] = __float2half_rn(w - __half2float(hi));   // true residual
    g_w2h[i]  = __float2half_rn(W2[i]);
}

__global__ void __launch_bounds__(256) quant_h_kernel(){
    int row = blockIdx.x;
    int tid = threadIdx.x;
    const float* hr = g_h + (size_t)row * QH;
    float v[18]; float mx = 0.f;
#pragma unroll
    for (int i = 0; i < 18; i++){
        v[i] = hr[tid + i*256];
        mx = fmaxf(mx, fabsf(v[i]));
    }
#pragma unroll
    for (int o = 16; o > 0; o >>= 1) mx = fmaxf(mx, __shfl_xor_sync(0xffffffffu, mx, o));
    __shared__ float wmax[8];
    if ((tid & 31) == 0) wmax[tid >> 5] = mx;
    __syncthreads();
    mx = 0.f;
#pragma unroll
    for (int i = 0; i < 8; i++) mx = fmaxf(mx, wmax[i]);
    float s = fmaxf(mx * (1.0f/127.0f), 1e-8f);
    if (tid == 0) g_scale2[row] = s;
    __half* qr = g_q2 + (size_t)row * QH;
#pragma unroll
    for (int i = 0; i < 18; i++){
        int d = tid + i*256;
        float q = rintf(v[i] / s);
        q = fminf(fmaxf(q, -128.f), 127.f);
        qr[d] = __float2half_rn(q);
    }
}

// ---------------- HMMA GEMM: CTA 256x128x32, 8 warps (4m x 2n), warp 64x64 ----
constexpr int BM = 256, BN = 128, BK = 32;
constexpr int ATILE = BM * 64;   // 16 KB
constexpr int BTILE = BN * 64;   // 8 KB
constexpr int STAGES = 3;
constexpr int GM = 16;           // m-group for grid swizzle

template<bool FC1>
__global__ void __launch_bounds__(256, 1)
gemm_kernel(const float* __restrict__ bias, float* __restrict__ outArg){
    const __half* __restrict__ A   = FC1 ? g_q1   : g_q2;
    const __half* __restrict__ Bh  = FC1 ? g_w1hi : g_w2h;
    const __half* __restrict__ Bl  = g_w1lo;
    const float*  __restrict__ rsc = FC1 ? g_scale1 : g_scale2;
    float* __restrict__ outF       = FC1 ? (float*)g_h : outArg;
    const int K = FC1 ? QD : QH;
    const int N = FC1 ? QH : QD;
    const int nB = N / BN;
    const int NK = K / BK;

    // grid swizzle: groups of GM m-blocks, n fastest within group
    int bid = blockIdx.x;
    int per = GM * nB;
    int grp = bid / per, rem = bid % per;
    int m0 = (grp * GM + (rem % GM)) * BM;
    int n0 = (rem / GM) * BN;

    extern __shared__ __align__(128) char smem[];
    uint32_t sAb  = smem_u32(smem);                        // STAGES x 16KB
    uint32_t sBhb = sAb + STAGES*ATILE;                    // STAGES x 8KB
    uint32_t sBlb = sBhb + STAGES*BTILE;                   // STAGES x 8KB (FC1)

    int tid = threadIdx.x;
    int lane = tid & 31, wid = tid >> 5;
    int wm = wid >> 1, wn = wid & 1;                       // 4 x 2 warps

    float acc[4][8][4];
#pragma unroll
    for (int mt=0; mt<4; mt++)
#pragma unroll
        for (int nt=0; nt<8; nt++)
#pragma unroll
            for (int j=0; j<4; j++) acc[mt][nt][j] = 0.f;

    auto load_stage = [&](int kt, int st){
        size_t k0 = (size_t)kt * BK;
        uint32_t sA = sAb + st*ATILE;
        uint32_t sB = sBhb + st*BTILE;
        uint32_t sL = sBlb + st*BTILE;
#pragma unroll
        for (int i = 0; i < 4; i++){            // A: 1024 chunks
            int ch = tid + i*256;
            int r = ch >> 2, c = ch & 3;
            cp16(sA + sw_off(r,c), A + (size_t)(m0 + r)*K + k0 + c*8);
        }
#pragma unroll
        for (int i = 0; i < 2; i++){            // B: 512 chunks
            int ch = tid + i*256;
            int r = ch >> 2, c = ch & 3;
            uint32_t so = sw_off(r,c);
            const size_t go = (size_t)(n0 + r)*K + k0 + c*8;
            cp16(sB + so, Bh + go);
            if (FC1) cp16(sL + so, Bl + go);
        }
    };

    auto compute = [&](int st){
        uint32_t sA = sAb + st*ATILE;
        uint32_t sB = sBhb + st*BTILE;
        uint32_t sL = sBlb + st*BTILE;
#pragma unroll
        for (int kt = 0; kt < 2; kt++){
            uint32_t a[4][4];
#pragma unroll
            for (int mt = 0; mt < 4; mt++){
                int r = wm*64 + mt*16 + (lane & 15);
                int c = kt*2 + (lane >> 4);
                ldsm_x4(a[mt], sA + sw_off(r, c));
            }
            int rb = wn*64 + ((lane >> 4) << 3) + (lane & 7);
            int cb = kt*2 + ((lane >> 3) & 1);
            uint32_t b[4][4];
#pragma unroll
            for (int p = 0; p < 4; p++)
                ldsm_x4(b[p], sB + sw_off(rb + p*16, cb));
#pragma unroll
            for (int mt = 0; mt < 4; mt++)
#pragma unroll
                for (int p = 0; p < 4; p++){
                    mma16816(acc[mt][p*2+0], a[mt], &b[p][0]);
                    mma16816(acc[mt][p*2+1], a[mt], &b[p][2]);
                }
            if (FC1){
#pragma unroll
                for (int p = 0; p < 4; p++)
                    ldsm_x4(b[p], sL + sw_off(rb + p*16, cb));
#pragma unroll
                for (int mt = 0; mt < 4; mt++)
#pragma unroll
                    for (int p = 0; p < 4; p++){
                        mma16816(acc[mt][p*2+0], a[mt], &b[p][0]);
                        mma16816(acc[mt][p*2+1], a[mt], &b[p][2]);
                    }
            }
        }
    };

    load_stage(0, 0); CP_COMMIT();
    load_stage(1, 1); CP_COMMIT();
    for (int kt = 0; kt < NK; kt++){
        int st = kt % 3;
        if (kt + 2 < NK){
            load_stage(kt + 2, (kt + 2) % 3);
            CP_COMMIT();
            CP_WAIT(2);
        } else if (kt + 1 < NK){
            CP_WAIT(1);
        } else {
            CP_WAIT(0);
        }
        __syncthreads();
        compute(st);
        __syncthreads();
    }

    // ---- epilogue ----
#pragma unroll
    for (int mt = 0; mt < 4; mt++){
#pragma unroll
        for (int hf = 0; hf < 2; hf++){
            int row = m0 + wm*64 + mt*16 + (lane >> 2) + 8*hf;
            float s = __ldg(rsc + row);
#pragma unroll
            for (int nt = 0; nt < 8; nt++){
                int col = n0 + wn*64 + nt*8 + (lane & 3)*2;
                float v0 = acc[mt][nt][hf*2 + 0] * s + __ldg(bias + col);
                float v1 = acc[mt][nt][hf*2 + 1] * s + __ldg(bias + col + 1);
                if (FC1){
                    v0 = gelu_exact(v0);
                    v1 = gelu_exact(v1);
                }
                *(float2*)(outF + (size_t)row * N + col) = make_float2(v0, v1);
            }
        }
    }
}

// ---------------- launch ----------------
extern "C" void kernel_launch(void* const* d_in, const int* in_sizes, int n_in,
                              void* d_out, int out_size){
    (void)in_sizes; (void)n_in; (void)out_size;
    const float* x    = (const float*)d_in[0];
    const int*   ridx = (const int*)  d_in[1];
    const float* W1   = (const float*)d_in[2];
    const float* b1   = (const float*)d_in[3];
    const float* W2   = (const float*)d_in[4];
    const float* b2   = (const float*)d_in[5];
    float* out = (float*)d_out;

    const int SMEM1 = STAGES * (ATILE + 2*BTILE);  // 96 KB
    const int SMEM2 = STAGES * (ATILE + BTILE);    // 72 KB
    cudaFuncSetAttribute(gemm_kernel<true>,  cudaFuncAttributeMaxDynamicSharedMemorySize, SMEM1);
    cudaFuncSetAttribute(gemm_kernel<false>, cudaFuncAttributeMaxDynamicSharedMemorySize, SMEM2);

    quant_x_kernel<<<QM, 128>>>(x, ridx);
    {
        size_t Nw = (size_t)QH * QD;
        convert_w_kernel<<<(unsigned)((Nw + 255) / 256), 256>>>(W1, W2);
    }
    gemm_kernel<true> <<<(QH/BN) * (QM/BM), 256, SMEM1>>>(b1, nullptr);
    quant_h_kernel<<<QM, 256>>>();
    gemm_kernel<false><<<(QD/BN) * (QM/BM), 256, SMEM2>>>(b2, out);
}